// round 1
// baseline (speedup 1.0000x reference)
#include <cuda_runtime.h>
#include <cstdint>

#define N_NODES 100000
#define N_EDGES 1250000
#define IN_CH   128
#define HID_CH  64
#define CLS_CH  32

// Scratch (alloc-free rule: device globals)
__device__ __align__(16) float g_h1  [(size_t)N_NODES * HID_CH]; // x @ W1
__device__ __align__(16) float g_agg1[(size_t)N_NODES * HID_CH]; // scatter-sum of g_h1
__device__ __align__(16) float g_m2  [(size_t)N_NODES * CLS_CH]; // relu(agg1+b1) @ W2

// ---------------- packed f32x2 helpers ----------------
__device__ __forceinline__ unsigned long long pack2(float a, float b) {
    unsigned long long r;
    asm("mov.b64 %0, {%1, %2};" : "=l"(r) : "f"(a), "f"(b));
    return r;
}
__device__ __forceinline__ unsigned long long fma2(unsigned long long a,
                                                   unsigned long long b,
                                                   unsigned long long c) {
    unsigned long long d;
    asm("fma.rn.f32x2 %0, %1, %2, %3;" : "=l"(d) : "l"(a), "l"(b), "l"(c));
    return d;
}

// ---------------- K0: zero accumulators ----------------
__global__ void k_zero(float* __restrict__ out) {
    int i = blockIdx.x * blockDim.x + threadIdx.x;
    float4 z = make_float4(0.f, 0.f, 0.f, 0.f);
    if (i < N_NODES * HID_CH / 4) reinterpret_cast<float4*>(g_agg1)[i] = z;
    if (i < N_NODES * CLS_CH / 4) reinterpret_cast<float4*>(out)[i]    = z;
}

// ---------------- K1: h1 = x @ W1 (128 -> 64) ----------------
// One thread per row; W1 staged in shared; packed f32x2 FMA.
__global__ __launch_bounds__(256) void k_gemm1(const float* __restrict__ x,
                                               const float* __restrict__ W1) {
    __shared__ ulonglong2 sW[IN_CH][HID_CH / 4];   // 32 KB, [k][c4] = 4 consecutive out-ch
    for (int i = threadIdx.x; i < IN_CH * HID_CH / 4; i += 256)
        reinterpret_cast<ulonglong2*>(sW)[i] = reinterpret_cast<const ulonglong2*>(W1)[i];
    __syncthreads();

    int row = blockIdx.x * 256 + threadIdx.x;
    if (row >= N_NODES) return;

    unsigned long long acc[HID_CH / 2];
#pragma unroll
    for (int i = 0; i < HID_CH / 2; i++) acc[i] = 0ull;

    const float4* xr = reinterpret_cast<const float4*>(x + (size_t)row * IN_CH);
    for (int kk = 0; kk < IN_CH / 4; kk++) {
        float4 xv = __ldg(xr + kk);
#pragma unroll
        for (int j = 0; j < 4; j++) {
            float xs = (j == 0) ? xv.x : (j == 1) ? xv.y : (j == 2) ? xv.z : xv.w;
            unsigned long long xx = pack2(xs, xs);
            int k = kk * 4 + j;
#pragma unroll
            for (int c4 = 0; c4 < HID_CH / 4; c4++) {
                ulonglong2 w = sW[k][c4];
                acc[2 * c4 + 0] = fma2(xx, w.x, acc[2 * c4 + 0]);
                acc[2 * c4 + 1] = fma2(xx, w.y, acc[2 * c4 + 1]);
            }
        }
    }
    ulonglong2* o = reinterpret_cast<ulonglong2*>(g_h1 + (size_t)row * HID_CH);
#pragma unroll
    for (int c4 = 0; c4 < HID_CH / 4; c4++) {
        ulonglong2 v; v.x = acc[2 * c4]; v.y = acc[2 * c4 + 1];
        o[c4] = v;
    }
}

// ---------------- K2: agg1[dst] += h1[src]  (64 ch, 16 lanes/edge) ----------------
__global__ __launch_bounds__(256) void k_scatter1(const int* __restrict__ src,
                                                  const int* __restrict__ dst) {
    int t = blockIdx.x * 256 + threadIdx.x;
    int e = t >> 4;
    if (e >= N_EDGES) return;
    int lane = t & 15;
    int s = __ldg(src + e);
    int d = __ldg(dst + e);
    float4 v = reinterpret_cast<const float4*>(g_h1 + (size_t)s * HID_CH)[lane];
    float* p = g_agg1 + (size_t)d * HID_CH + lane * 4;
    asm volatile("red.global.add.v4.f32 [%0], {%1, %2, %3, %4};"
                 :: "l"(p), "f"(v.x), "f"(v.y), "f"(v.z), "f"(v.w) : "memory");
}

// ---------------- K3: m2 = relu(agg1 + b1) @ W2 (64 -> 32) ----------------
__global__ __launch_bounds__(256) void k_gemm2(const float* __restrict__ W2,
                                               const float* __restrict__ b1) {
    __shared__ ulonglong2 sW[HID_CH][CLS_CH / 4];  // 8 KB
    __shared__ float sb1[HID_CH];
    for (int i = threadIdx.x; i < HID_CH * CLS_CH / 4; i += 256)
        reinterpret_cast<ulonglong2*>(sW)[i] = reinterpret_cast<const ulonglong2*>(W2)[i];
    if (threadIdx.x < HID_CH) sb1[threadIdx.x] = b1[threadIdx.x];
    __syncthreads();

    int row = blockIdx.x * 256 + threadIdx.x;
    if (row >= N_NODES) return;

    unsigned long long acc[CLS_CH / 2];
#pragma unroll
    for (int i = 0; i < CLS_CH / 2; i++) acc[i] = 0ull;

    const float4* ar = reinterpret_cast<const float4*>(g_agg1 + (size_t)row * HID_CH);
    for (int kk = 0; kk < HID_CH / 4; kk++) {
        float4 av = ar[kk];
#pragma unroll
        for (int j = 0; j < 4; j++) {
            float a = (j == 0) ? av.x : (j == 1) ? av.y : (j == 2) ? av.z : av.w;
            int k = kk * 4 + j;
            float tval = fmaxf(a + sb1[k], 0.f);
            unsigned long long xx = pack2(tval, tval);
#pragma unroll
            for (int c4 = 0; c4 < CLS_CH / 4; c4++) {
                ulonglong2 w = sW[k][c4];
                acc[2 * c4 + 0] = fma2(xx, w.x, acc[2 * c4 + 0]);
                acc[2 * c4 + 1] = fma2(xx, w.y, acc[2 * c4 + 1]);
            }
        }
    }
    ulonglong2* o = reinterpret_cast<ulonglong2*>(g_m2 + (size_t)row * CLS_CH);
#pragma unroll
    for (int c4 = 0; c4 < CLS_CH / 4; c4++) {
        ulonglong2 v; v.x = acc[2 * c4]; v.y = acc[2 * c4 + 1];
        o[c4] = v;
    }
}

// ---------------- K4: out[dst] += m2[src]  (32 ch, 8 lanes/edge) ----------------
__global__ __launch_bounds__(256) void k_scatter2(const int* __restrict__ src,
                                                  const int* __restrict__ dst,
                                                  float* __restrict__ out) {
    int t = blockIdx.x * 256 + threadIdx.x;
    int e = t >> 3;
    if (e >= N_EDGES) return;
    int lane = t & 7;
    int s = __ldg(src + e);
    int d = __ldg(dst + e);
    float4 v = reinterpret_cast<const float4*>(g_m2 + (size_t)s * CLS_CH)[lane];
    float* p = out + (size_t)d * CLS_CH + lane * 4;
    asm volatile("red.global.add.v4.f32 [%0], {%1, %2, %3, %4};"
                 :: "l"(p), "f"(v.x), "f"(v.y), "f"(v.z), "f"(v.w) : "memory");
}

// ---------------- K5: out = sigmoid(out + b2) ----------------
__global__ void k_final(float* __restrict__ out, const float* __restrict__ b2) {
    int i = blockIdx.x * blockDim.x + threadIdx.x;
    if (i >= N_NODES * CLS_CH / 4) return;
    float4 v = reinterpret_cast<float4*>(out)[i];
    float4 b = reinterpret_cast<const float4*>(b2)[i & 7];
    v.x = 1.f / (1.f + __expf(-(v.x + b.x)));
    v.y = 1.f / (1.f + __expf(-(v.y + b.y)));
    v.z = 1.f / (1.f + __expf(-(v.z + b.z)));
    v.w = 1.f / (1.f + __expf(-(v.w + b.w)));
    reinterpret_cast<float4*>(out)[i] = v;
}

extern "C" void kernel_launch(void* const* d_in, const int* in_sizes, int n_in,
                              void* d_out, int out_size) {
    const float* x  = (const float*)d_in[0];
    const int*   ei = (const int*)  d_in[1];
    const float* W1 = (const float*)d_in[2];
    const float* b1 = (const float*)d_in[3];
    const float* W2 = (const float*)d_in[4];
    const float* b2 = (const float*)d_in[5];
    float* out = (float*)d_out;
    const int* src = ei;
    const int* dst = ei + N_EDGES;

    k_zero<<<(N_NODES * HID_CH / 4 + 255) / 256, 256>>>(out);
    k_gemm1<<<(N_NODES + 255) / 256, 256>>>(x, W1);
    k_scatter1<<<(N_EDGES * 16 + 255) / 256, 256>>>(src, dst);
    k_gemm2<<<(N_NODES + 255) / 256, 256>>>(W2, b1);
    k_scatter2<<<(N_EDGES * 8 + 255) / 256, 256>>>(src, dst, out);
    k_final<<<(N_NODES * CLS_CH / 4 + 255) / 256, 256>>>(out, b2);
}

// round 2
// speedup vs baseline: 1.0642x; 1.0642x over previous
#include <cuda_runtime.h>
#include <cstdint>

#define N_NODES 100000
#define N_EDGES 1250000
#define IN_CH   128
#define HID_CH  64
#define CLS_CH  32
#define SCAN_B  1024
#define NB      98        // ceil(N_NODES / SCAN_B)

// ---------------- scratch (device globals; alloc-free rule) ----------------
__device__ __align__(16) float g_h1  [(size_t)N_NODES * HID_CH]; // x @ W1
__device__ __align__(16) float g_act1[(size_t)N_NODES * HID_CH]; // relu(A@h1 + b1)
__device__ __align__(16) float g_m2  [(size_t)N_NODES * CLS_CH]; // act1 @ W2
__device__ int g_deg   [N_NODES];
__device__ int g_incl  [N_NODES];
__device__ int g_off   [N_NODES];
__device__ int g_cursor[N_NODES];
__device__ int g_bsum  [128];
__device__ int g_bbase [128];
__device__ int g_csr_src[N_EDGES];

// ---------------- packed f32x2 helpers ----------------
__device__ __forceinline__ unsigned long long pack2(float a, float b) {
    unsigned long long r;
    asm("mov.b64 %0, {%1, %2};" : "=l"(r) : "f"(a), "f"(b));
    return r;
}
__device__ __forceinline__ unsigned long long fma2(unsigned long long a,
                                                   unsigned long long b,
                                                   unsigned long long c) {
    unsigned long long d;
    asm("fma.rn.f32x2 %0, %1, %2, %3;" : "=l"(d) : "l"(a), "l"(b), "l"(c));
    return d;
}

// ---------------- K: zero counters ----------------
__global__ void k_zero_cnt() {
    int i = blockIdx.x * blockDim.x + threadIdx.x;
    if (i < N_NODES) { g_deg[i] = 0; g_cursor[i] = 0; }
}

// ---------------- K: degree histogram ----------------
__global__ void k_hist(const int* __restrict__ dst) {
    int e = blockIdx.x * blockDim.x + threadIdx.x;
    if (e < N_EDGES) atomicAdd(&g_deg[__ldg(dst + e)], 1);   // no return use -> RED
}

// ---------------- K: scan pass 1 (per-block inclusive) ----------------
__global__ __launch_bounds__(SCAN_B) void k_scan1() {
    __shared__ int s[SCAN_B];
    int tid = threadIdx.x;
    int i = blockIdx.x * SCAN_B + tid;
    int v = (i < N_NODES) ? g_deg[i] : 0;
    s[tid] = v;
    __syncthreads();
#pragma unroll
    for (int ofs = 1; ofs < SCAN_B; ofs <<= 1) {
        int t = (tid >= ofs) ? s[tid - ofs] : 0;
        __syncthreads();
        s[tid] += t;
        __syncthreads();
    }
    if (i < N_NODES) g_incl[i] = s[tid];
    if (tid == SCAN_B - 1) g_bsum[blockIdx.x] = s[tid];
}

// ---------------- K: scan pass 2 (block sums, one block) ----------------
__global__ void k_scan2() {
    __shared__ int s[128];
    int tid = threadIdx.x;
    int v = (tid < NB) ? g_bsum[tid] : 0;
    s[tid] = v;
    __syncthreads();
#pragma unroll
    for (int ofs = 1; ofs < 128; ofs <<= 1) {
        int t = (tid >= ofs) ? s[tid - ofs] : 0;
        __syncthreads();
        s[tid] += t;
        __syncthreads();
    }
    if (tid < NB) g_bbase[tid] = s[tid] - v;   // exclusive base for block tid
}

// ---------------- K: scan pass 3 (final exclusive offsets) ----------------
__global__ void k_scan3() {
    int i = blockIdx.x * blockDim.x + threadIdx.x;
    if (i < N_NODES)
        g_off[i] = g_incl[i] - g_deg[i] + g_bbase[i >> 10];
}

// ---------------- K: fill CSR source lists ----------------
__global__ void k_fill(const int* __restrict__ src, const int* __restrict__ dst) {
    int e = blockIdx.x * blockDim.x + threadIdx.x;
    if (e >= N_EDGES) return;
    int d = __ldg(dst + e);
    int pos = atomicAdd(&g_cursor[d], 1);
    g_csr_src[g_off[d] + pos] = __ldg(src + e);
}

// ---------------- K1: h1 = x @ W1 (128 -> 64), thread-per-row ----------------
__global__ __launch_bounds__(256) void k_gemm1(const float* __restrict__ x,
                                               const float* __restrict__ W1) {
    __shared__ ulonglong2 sW[IN_CH][HID_CH / 4];   // 32 KB
    for (int i = threadIdx.x; i < IN_CH * HID_CH / 4; i += 256)
        reinterpret_cast<ulonglong2*>(sW)[i] = reinterpret_cast<const ulonglong2*>(W1)[i];
    __syncthreads();

    int row = blockIdx.x * 256 + threadIdx.x;
    if (row >= N_NODES) return;

    unsigned long long acc[HID_CH / 2];
#pragma unroll
    for (int i = 0; i < HID_CH / 2; i++) acc[i] = 0ull;

    const float4* xr = reinterpret_cast<const float4*>(x + (size_t)row * IN_CH);
    for (int kk = 0; kk < IN_CH / 4; kk++) {
        float4 xv = __ldg(xr + kk);
#pragma unroll
        for (int j = 0; j < 4; j++) {
            float xs = (j == 0) ? xv.x : (j == 1) ? xv.y : (j == 2) ? xv.z : xv.w;
            unsigned long long xx = pack2(xs, xs);
            int k = kk * 4 + j;
#pragma unroll
            for (int c4 = 0; c4 < HID_CH / 4; c4++) {
                ulonglong2 w = sW[k][c4];
                acc[2 * c4 + 0] = fma2(xx, w.x, acc[2 * c4 + 0]);
                acc[2 * c4 + 1] = fma2(xx, w.y, acc[2 * c4 + 1]);
            }
        }
    }
    ulonglong2* o = reinterpret_cast<ulonglong2*>(g_h1 + (size_t)row * HID_CH);
#pragma unroll
    for (int c4 = 0; c4 < HID_CH / 4; c4++) {
        ulonglong2 v; v.x = acc[2 * c4]; v.y = acc[2 * c4 + 1];
        o[c4] = v;
    }
}

// ---------------- K: act1 = relu(A @ h1 + b1), warp-per-node gather ----------------
__global__ __launch_bounds__(256) void k_agg1(const float* __restrict__ b1) {
    int t = blockIdx.x * 256 + threadIdx.x;
    int node = t >> 5;
    if (node >= N_NODES) return;
    int lane = t & 31;

    int beg = g_off[node];
    int dg  = g_deg[node];

    float2 acc = make_float2(0.f, 0.f);
    for (int base = 0; base < dg; base += 32) {
        int idx = (base + lane < dg) ? __ldg(g_csr_src + beg + base + lane) : 0;
        int cnt = min(32, dg - base);
        for (int k = 0; k < cnt; k++) {
            int s = __shfl_sync(0xffffffffu, idx, k);
            float2 v = reinterpret_cast<const float2*>(g_h1 + (size_t)s * HID_CH)[lane];
            acc.x += v.x;
            acc.y += v.y;
        }
    }
    float2 b = reinterpret_cast<const float2*>(b1)[lane];
    acc.x = fmaxf(acc.x + b.x, 0.f);
    acc.y = fmaxf(acc.y + b.y, 0.f);
    reinterpret_cast<float2*>(g_act1 + (size_t)node * HID_CH)[lane] = acc;
}

// ---------------- K3: m2 = act1 @ W2 (64 -> 32), thread-per-row ----------------
__global__ __launch_bounds__(256) void k_gemm2(const float* __restrict__ W2) {
    __shared__ ulonglong2 sW[HID_CH][CLS_CH / 4];  // 8 KB
    for (int i = threadIdx.x; i < HID_CH * CLS_CH / 4; i += 256)
        reinterpret_cast<ulonglong2*>(sW)[i] = reinterpret_cast<const ulonglong2*>(W2)[i];
    __syncthreads();

    int row = blockIdx.x * 256 + threadIdx.x;
    if (row >= N_NODES) return;

    unsigned long long acc[CLS_CH / 2];
#pragma unroll
    for (int i = 0; i < CLS_CH / 2; i++) acc[i] = 0ull;

    const float4* ar = reinterpret_cast<const float4*>(g_act1 + (size_t)row * HID_CH);
    for (int kk = 0; kk < HID_CH / 4; kk++) {
        float4 av = ar[kk];
#pragma unroll
        for (int j = 0; j < 4; j++) {
            float a = (j == 0) ? av.x : (j == 1) ? av.y : (j == 2) ? av.z : av.w;
            int k = kk * 4 + j;
            unsigned long long xx = pack2(a, a);
#pragma unroll
            for (int c4 = 0; c4 < CLS_CH / 4; c4++) {
                ulonglong2 w = sW[k][c4];
                acc[2 * c4 + 0] = fma2(xx, w.x, acc[2 * c4 + 0]);
                acc[2 * c4 + 1] = fma2(xx, w.y, acc[2 * c4 + 1]);
            }
        }
    }
    ulonglong2* o = reinterpret_cast<ulonglong2*>(g_m2 + (size_t)row * CLS_CH);
#pragma unroll
    for (int c4 = 0; c4 < CLS_CH / 4; c4++) {
        ulonglong2 v; v.x = acc[2 * c4]; v.y = acc[2 * c4 + 1];
        o[c4] = v;
    }
}

// ---------------- K: out = sigmoid(A @ m2 + b2), warp-per-node gather ----------------
__global__ __launch_bounds__(256) void k_agg2(const float* __restrict__ b2,
                                              float* __restrict__ out) {
    int t = blockIdx.x * 256 + threadIdx.x;
    int node = t >> 5;
    if (node >= N_NODES) return;
    int lane = t & 31;

    int beg = g_off[node];
    int dg  = g_deg[node];

    float acc = 0.f;
    for (int base = 0; base < dg; base += 32) {
        int idx = (base + lane < dg) ? __ldg(g_csr_src + beg + base + lane) : 0;
        int cnt = min(32, dg - base);
        for (int k = 0; k < cnt; k++) {
            int s = __shfl_sync(0xffffffffu, idx, k);
            acc += g_m2[(size_t)s * CLS_CH + lane];
        }
    }
    float v = acc + __ldg(b2 + lane);
    out[(size_t)node * CLS_CH + lane] = 1.f / (1.f + __expf(-v));
}

extern "C" void kernel_launch(void* const* d_in, const int* in_sizes, int n_in,
                              void* d_out, int out_size) {
    const float* x  = (const float*)d_in[0];
    const int*   ei = (const int*)  d_in[1];
    const float* W1 = (const float*)d_in[2];
    const float* b1 = (const float*)d_in[3];
    const float* W2 = (const float*)d_in[4];
    const float* b2 = (const float*)d_in[5];
    float* out = (float*)d_out;
    const int* src = ei;
    const int* dst = ei + N_EDGES;

    // CSR build (per replay; deterministic up to fp-neutral edge order)
    k_zero_cnt<<<(N_NODES + 255) / 256, 256>>>();
    k_hist<<<(N_EDGES + 255) / 256, 256>>>(dst);
    k_scan1<<<NB, SCAN_B>>>();
    k_scan2<<<1, 128>>>();
    k_scan3<<<(N_NODES + 255) / 256, 256>>>();
    k_fill<<<(N_EDGES + 255) / 256, 256>>>(src, dst);

    // layer 1
    k_gemm1<<<(N_NODES + 255) / 256, 256>>>(x, W1);
    k_agg1<<<(N_NODES * 32 + 255) / 256, 256>>>(b1);
    // layer 2
    k_gemm2<<<(N_NODES + 255) / 256, 256>>>(W2);
    k_agg2<<<(N_NODES * 32 + 255) / 256, 256>>>(b2, out);
}